// round 11
// baseline (speedup 1.0000x reference)
#include <cuda_runtime.h>
#include <cuda_bf16.h>
#include <cuda_fp16.h>
#include <stdint.h>

#define NMAX 50000
#define EMAX 600000
#define D 128

// ======================= device scratch (no allocation) =======================
__device__ uint4  g_fhi4[NMAX * D / 8];       // bf16 hi of layer input
__device__ uint4  g_flo4[NMAX * D / 8];       // bf16 lo
__device__ uint4  g_Whi4[8 * D * D / 8];      // 8 weight matrices bf16 hi [l*2 + {0:W1,1:W0}]
__device__ uint4  g_Wlo4[8 * D * D / 8];
__device__ __half g_hA[NMAX * D];             // h ping (fp16)
__device__ __half g_hB[NMAX * D];             // h pong
__device__ float4 g_rawA[NMAX * D / 4];       // raw ping
__device__ float4 g_rawB[NMAX * D / 4];       // raw pong
__device__ int    g_cnt[NMAX];
__device__ int    g_cursor[NMAX];
__device__ int    g_rowptr[NMAX + 1];
__device__ float  g_invdeg[NMAX];
__device__ int    g_adj[2 * EMAX];            // after sortseg: BYTE offsets (nb*256)

// ======================= bf16 hi/lo split =======================
__device__ __forceinline__ void split4(float4 v, uint2& hi, uint2& lo) {
    __nv_bfloat16 hx = __float2bfloat16_rn(v.x);
    __nv_bfloat16 hy = __float2bfloat16_rn(v.y);
    __nv_bfloat16 hz = __float2bfloat16_rn(v.z);
    __nv_bfloat16 hw = __float2bfloat16_rn(v.w);
    __nv_bfloat16 lx = __float2bfloat16_rn(v.x - __bfloat162float(hx));
    __nv_bfloat16 ly = __float2bfloat16_rn(v.y - __bfloat162float(hy));
    __nv_bfloat16 lz = __float2bfloat16_rn(v.z - __bfloat162float(hz));
    __nv_bfloat16 lw = __float2bfloat16_rn(v.w - __bfloat162float(hw));
    __nv_bfloat162 h01 = __halves2bfloat162(hx, hy);
    __nv_bfloat162 h23 = __halves2bfloat162(hz, hw);
    __nv_bfloat162 l01 = __halves2bfloat162(lx, ly);
    __nv_bfloat162 l23 = __halves2bfloat162(lz, lw);
    hi.x = *(uint32_t*)&h01; hi.y = *(uint32_t*)&h23;
    lo.x = *(uint32_t*)&l01; lo.y = *(uint32_t*)&l23;
}

__global__ void k_conv(const float* __restrict__ features,
                       const float* __restrict__ W0f, const float* __restrict__ W1f,
                       const float* __restrict__ W0h, const float* __restrict__ W1h,
                       int Nn) {
    int i = blockIdx.x * blockDim.x + threadIdx.x;
    if (i < Nn * 32) {
        float4 v = ((const float4*)features)[i];
        uint2 hi, lo;
        split4(v, hi, lo);
        ((uint2*)g_fhi4)[i] = hi;
        ((uint2*)g_flo4)[i] = lo;
    }
    if (i < 8 * 4096) {
        int m = i >> 12;
        int off = i & 4095;
        int l = m >> 1;
        int isW0 = m & 1;
        const float* src = (l == 0) ? (isW0 ? W0f : W1f)
                                    : (isW0 ? W0h + (size_t)(l - 1) * D * D
                                            : W1h + (size_t)(l - 1) * D * D);
        float4 v = ((const float4*)src)[off];
        uint2 hi, lo;
        split4(v, hi, lo);
        ((uint2*)g_Whi4)[(size_t)m * 4096 + off] = hi;
        ((uint2*)g_Wlo4)[(size_t)m * 4096 + off] = lo;
    }
}

// ======================= CSR build =======================
__global__ void k_count(const int* __restrict__ edges, int E) {
    int e = blockIdx.x * blockDim.x + threadIdx.x;
    if (e < E) {
        atomicAdd(&g_cnt[edges[2 * e]], 1);
        atomicAdd(&g_cnt[edges[2 * e + 1]], 1);
    }
}

__global__ void k_scan(int n) {
    __shared__ int ss[1024];
    int t = threadIdx.x;
    int chunk = (n + 1023) >> 10;
    int b = t * chunk;
    int e = min(b + chunk, n);
    int s = 0;
    for (int i = b; i < e; i++) s += g_cnt[i];
    ss[t] = s;
    __syncthreads();
    for (int off = 1; off < 1024; off <<= 1) {
        int add = (t >= off) ? ss[t - off] : 0;
        __syncthreads();
        ss[t] += add;
        __syncthreads();
    }
    int run = (t == 0) ? 0 : ss[t - 1];
    for (int i = b; i < e; i++) {
        g_rowptr[i] = run;
        g_cursor[i] = run;
        int c = g_cnt[i];
        g_invdeg[i] = 1.0f / (float)(c > 0 ? c : 1);
        run += c;
    }
    if (t == 1023) g_rowptr[n] = ss[1023];
}

__global__ void k_fill(const int* __restrict__ edges, int E) {
    int e = blockIdx.x * blockDim.x + threadIdx.x;
    if (e < E) {
        int s = edges[2 * e];
        int d = edges[2 * e + 1];
        g_adj[atomicAdd(&g_cursor[s], 1)] = d;
        g_adj[atomicAdd(&g_cursor[d], 1)] = s;
    }
}

// deterministic adjacency order (sorted) + convert to byte offsets (nb*256)
#define SORT_BUF 96
__global__ void k_sortseg(int n) {
    int i = blockIdx.x * blockDim.x + threadIdx.x;
    if (i >= n) return;
    int b = g_rowptr[i], e = g_rowptr[i + 1];
    int len = e - b;
    if (len <= 0) return;
    if (len <= SORT_BUF) {
        int buf[SORT_BUF];
        for (int j = 0; j < len; j++) buf[j] = g_adj[b + j];
        for (int j = 1; j < len; j++) {
            int key = buf[j];
            int k = j - 1;
            while (k >= 0 && buf[k] > key) { buf[k + 1] = buf[k]; --k; }
            buf[k + 1] = key;
        }
        for (int j = 0; j < len; j++) g_adj[b + j] = buf[j] << 8;   // *256
    } else {
        for (int j = b + 1; j < e; j++) {
            int key = g_adj[j];
            int k = j - 1;
            while (k >= b && g_adj[k] > key) { g_adj[k + 1] = g_adj[k]; --k; }
            g_adj[k + 1] = key;
        }
        for (int j = b; j < e; j++) g_adj[j] <<= 8;
    }
}

// ======================= tensor-core fused GEMM (mma.sync bf16) ================
// R10 interior, + rowStart for split launches.
#define SROW 272
#define STILE (128 * SROW)
#define SM_A_HI  0
#define SM_A_LO  (STILE)
#define SM_W1HI  (2 * STILE)
#define SM_W1LO  (3 * STILE)
#define SM_W0HI  (4 * STILE)
#define SM_W0LO  (5 * STILE)
#define SMEM_MM_TOTAL (6 * STILE)          // 208896 B

__device__ __forceinline__ uint32_t smem_to_u32(const void* smem_ptr) {
    uint32_t addr;
    asm("{ .reg .u64 tmp; cvta.to.shared.u64 tmp, %1; cvt.u32.u64 %0, tmp; }"
        : "=r"(addr) : "l"(smem_ptr));
    return addr;
}

__device__ __forceinline__ void ldm_x4(uint32_t* r, uint32_t addr) {
    asm volatile("ldmatrix.sync.aligned.m8n8.x4.shared.b16 {%0,%1,%2,%3}, [%4];"
        : "=r"(r[0]), "=r"(r[1]), "=r"(r[2]), "=r"(r[3]) : "r"(addr));
}

__device__ __forceinline__ void mma16816(float* c, const uint32_t* a, const uint32_t* b) {
    asm volatile(
        "mma.sync.aligned.m16n8k16.row.col.f32.bf16.bf16.f32 "
        "{%0,%1,%2,%3}, {%4,%5,%6,%7}, {%8,%9}, {%0,%1,%2,%3};"
        : "+f"(c[0]), "+f"(c[1]), "+f"(c[2]), "+f"(c[3])
        : "r"(a[0]), "r"(a[1]), "r"(a[2]), "r"(a[3]), "r"(b[0]), "r"(b[1]));
}

__global__ void __launch_bounds__(512, 1)
k_mm(const uint4* __restrict__ fhi, const uint4* __restrict__ flo,
     const uint4* __restrict__ w1hi, const uint4* __restrict__ w1lo,
     const uint4* __restrict__ w0hi, const uint4* __restrict__ w0lo,
     __half* __restrict__ hout, float* __restrict__ rawout, int rowStart, int M) {
    extern __shared__ char smem[];
    const int tid = threadIdx.x;
    const int wid = tid >> 5;
    const int lane = tid & 31;
    const int ph = wid >> 3;
    const int w8 = wid & 7;
    const int wm = w8 >> 1;
    const int wn = w8 & 1;
    const int rowBase = rowStart + blockIdx.x * 128;

    const uint4 z4 = make_uint4(0, 0, 0, 0);
#pragma unroll 4
    for (int i = tid; i < 2048; i += 512) {
        int r = i >> 4, c = i & 15;
        uint32_t off = (uint32_t)r * SROW + (uint32_t)c * 16;
        bool ok = (rowBase + r) < M;
        size_t gi = (size_t)rowBase * 16 + i;
        *(uint4*)(smem + SM_A_HI + off) = ok ? fhi[gi] : z4;
        *(uint4*)(smem + SM_A_LO + off) = ok ? flo[gi] : z4;
        *(uint4*)(smem + SM_W1HI + off) = w1hi[i];
        *(uint4*)(smem + SM_W1LO + off) = w1lo[i];
        *(uint4*)(smem + SM_W0HI + off) = w0hi[i];
        *(uint4*)(smem + SM_W0LO + off) = w0lo[i];
    }
    __syncthreads();

    uint32_t sb = smem_to_u32(smem);
    const uint32_t aRowOff = (uint32_t)(wm * 32 + (lane & 15)) * SROW + ((lane >> 4) << 4);
    const uint32_t bRowCore = (uint32_t)(((lane >> 4) << 3) + (lane & 7)) * SROW
                            + (((lane >> 3) & 1) << 4);
    const int g = lane >> 2, tg = lane & 3;

    uint32_t wHi = sb + (ph ? SM_W0HI : SM_W1HI);
    uint32_t wLo = sb + (ph ? SM_W0LO : SM_W1LO);
    uint32_t aHiB = sb + SM_A_HI, aLoB = sb + SM_A_LO;

    float acc[2][8][4];
#pragma unroll
    for (int mt = 0; mt < 2; mt++)
#pragma unroll
        for (int nt = 0; nt < 8; nt++)
#pragma unroll
            for (int q = 0; q < 4; q++) acc[mt][nt][q] = 0.f;

#pragma unroll 1
    for (int ks = 0; ks < 8; ks++) {
        uint32_t kb = (uint32_t)ks * 32;
        uint32_t aH[2][4], aL[2][4];
        ldm_x4(aH[0], aHiB + aRowOff + kb);
        ldm_x4(aH[1], aHiB + aRowOff + 16 * SROW + kb);
        ldm_x4(aL[0], aLoB + aRowOff + kb);
        ldm_x4(aL[1], aLoB + aRowOff + 16 * SROW + kb);
        uint32_t bH[8][2], bL[8][2];
#pragma unroll
        for (int np = 0; np < 4; np++) {
            uint32_t rowoff = (uint32_t)(wn * 64 + np * 16) * SROW + bRowCore + kb;
            uint32_t tmp[4];
            ldm_x4(tmp, wHi + rowoff);
            bH[np * 2][0] = tmp[0]; bH[np * 2][1] = tmp[1];
            bH[np * 2 + 1][0] = tmp[2]; bH[np * 2 + 1][1] = tmp[3];
            ldm_x4(tmp, wLo + rowoff);
            bL[np * 2][0] = tmp[0]; bL[np * 2][1] = tmp[1];
            bL[np * 2 + 1][0] = tmp[2]; bL[np * 2 + 1][1] = tmp[3];
        }
#pragma unroll
        for (int mt = 0; mt < 2; mt++)
#pragma unroll
            for (int nt = 0; nt < 8; nt++) {
                mma16816(acc[mt][nt], aH[mt], bH[nt]);   // hi*hi
                mma16816(acc[mt][nt], aH[mt], bL[nt]);   // hi*lo
                mma16816(acc[mt][nt], aL[mt], bH[nt]);   // lo*hi
            }
    }

#pragma unroll
    for (int mt = 0; mt < 2; mt++) {
        int row0 = rowBase + wm * 32 + mt * 16 + g;
#pragma unroll
        for (int nt = 0; nt < 8; nt++) {
            int col = wn * 64 + nt * 8 + tg * 2;
            if (ph == 0) {
                if (row0 < M)
                    *(__half2*)(hout + (size_t)row0 * 128 + col) =
                        __floats2half2_rn(acc[mt][nt][0], acc[mt][nt][1]);
                if (row0 + 8 < M)
                    *(__half2*)(hout + (size_t)(row0 + 8) * 128 + col) =
                        __floats2half2_rn(acc[mt][nt][2], acc[mt][nt][3]);
            } else {
                if (row0 < M)
                    *(float2*)(rawout + (size_t)row0 * 128 + col) =
                        make_float2(acc[mt][nt][0], acc[mt][nt][1]);
                if (row0 + 8 < M)
                    *(float2*)(rawout + (size_t)(row0 + 8) * 128 + col) =
                        make_float2(acc[mt][nt][2], acc[mt][nt][3]);
            }
        }
    }
}

// ============ fused aggregate + epilogue (R10 interior, node-range args) ============
__global__ void k_aggepi(const __half* __restrict__ h, const float4* __restrict__ raw,
                         const float* __restrict__ bias, const float4* __restrict__ res,
                         float4* __restrict__ outF,
                         uint2* __restrict__ fhi, uint2* __restrict__ flo,
                         int nodeStart, int nodeEnd, int mode) {
    int node = nodeStart + ((blockIdx.x * blockDim.x + threadIdx.x) >> 5);
    if (node >= nodeEnd) return;
    int lane = threadIdx.x & 31;
    int b = g_rowptr[node], e = g_rowptr[node + 1];
    const char* hb = (const char*)h;

    float4 acc[8];
#pragma unroll
    for (int q = 0; q < 8; q++) acc[q] = make_float4(0.f, 0.f, 0.f, 0.f);

    int p = b;
    for (; p + 8 <= e; p += 8) {
        int off[8];
#pragma unroll
        for (int q = 0; q < 8; q++) off[q] = g_adj[p + q];   // byte offsets
        uint2 u[8];
#pragma unroll
        for (int q = 0; q < 8; q++)
            u[q] = __ldcg((const uint2*)(hb + off[q]) + lane);
#pragma unroll
        for (int q = 0; q < 8; q++) {
            float2 x = __half22float2(*(__half2*)&u[q].x);
            float2 y = __half22float2(*(__half2*)&u[q].y);
            acc[q].x += x.x; acc[q].y += x.y; acc[q].z += y.x; acc[q].w += y.y;
        }
    }
    if (p + 4 <= e) {
        int off[4];
#pragma unroll
        for (int q = 0; q < 4; q++) off[q] = g_adj[p + q];
#pragma unroll
        for (int q = 0; q < 4; q++) {
            uint2 u = __ldcg((const uint2*)(hb + off[q]) + lane);
            float2 x = __half22float2(*(__half2*)&u.x);
            float2 y = __half22float2(*(__half2*)&u.y);
            acc[q].x += x.x; acc[q].y += x.y; acc[q].z += y.x; acc[q].w += y.y;
        }
        p += 4;
    }
    for (; p < e; ++p) {
        uint2 u = __ldcg((const uint2*)(hb + g_adj[p]) + lane);
        float2 x = __half22float2(*(__half2*)&u.x);
        float2 y = __half22float2(*(__half2*)&u.y);
        acc[0].x += x.x; acc[0].y += x.y; acc[0].z += y.x; acc[0].w += y.y;
    }

    float4 s01, s23, s45, s67, sA, sB, sum;
    s01.x = acc[0].x + acc[1].x; s01.y = acc[0].y + acc[1].y; s01.z = acc[0].z + acc[1].z; s01.w = acc[0].w + acc[1].w;
    s23.x = acc[2].x + acc[3].x; s23.y = acc[2].y + acc[3].y; s23.z = acc[2].z + acc[3].z; s23.w = acc[2].w + acc[3].w;
    s45.x = acc[4].x + acc[5].x; s45.y = acc[4].y + acc[5].y; s45.z = acc[4].z + acc[5].z; s45.w = acc[4].w + acc[5].w;
    s67.x = acc[6].x + acc[7].x; s67.y = acc[6].y + acc[7].y; s67.z = acc[6].z + acc[7].z; s67.w = acc[6].w + acc[7].w;
    sA.x = s01.x + s23.x; sA.y = s01.y + s23.y; sA.z = s01.z + s23.z; sA.w = s01.w + s23.w;
    sB.x = s45.x + s67.x; sB.y = s45.y + s67.y; sB.z = s45.z + s67.z; sB.w = s45.w + s67.w;
    sum.x = sA.x + sB.x; sum.y = sA.y + sB.y; sum.z = sA.z + sB.z; sum.w = sA.w + sB.w;

    float s = g_invdeg[node];
    size_t idx = (size_t)node * 32 + lane;
    float4 v = raw[idx];
    float4 bb = ((const float4*)bias)[lane];
    v.x += bb.x + sum.x * s;
    v.y += bb.y + sum.y * s;
    v.z += bb.z + sum.z * s;
    v.w += bb.w + sum.w * s;
    if (mode == 2) {
        float4 r = res[idx];
        v.x += r.x; v.y += r.y; v.z += r.z; v.w += r.w;
    }
    if (mode >= 1) {
        v.x = fmaxf(v.x, 0.f); v.y = fmaxf(v.y, 0.f);
        v.z = fmaxf(v.z, 0.f); v.w = fmaxf(v.w, 0.f);
    }
    if (mode == 2) {
        outF[idx] = v;
    } else {
        uint2 hi, lo;
        split4(v, hi, lo);
        fhi[idx] = hi;
        flo[idx] = lo;
    }
}

// ======================= launch =======================
extern "C" void kernel_launch(void* const* d_in, const int* in_sizes, int n_in,
                              void* d_out, int out_size) {
    const float* features = (const float*)d_in[0];
    const int*   edges    = (const int*)d_in[1];
    const float* W0f = (const float*)d_in[3];
    const float* W1f = (const float*)d_in[4];
    const float* bf  = (const float*)d_in[5];
    const float* W0h = (const float*)d_in[6];
    const float* W1h = (const float*)d_in[7];
    const float* bh  = (const float*)d_in[8];

    int Nn = in_sizes[0] / D;
    int Ee = in_sizes[1] / 2;

    uint4 *fhi, *flo, *whi, *wlo;
    __half *hP[2];
    float4 *rawP[2];
    int* cntp;
    cudaGetSymbolAddress((void**)&fhi, g_fhi4);
    cudaGetSymbolAddress((void**)&flo, g_flo4);
    cudaGetSymbolAddress((void**)&whi, g_Whi4);
    cudaGetSymbolAddress((void**)&wlo, g_Wlo4);
    cudaGetSymbolAddress((void**)&hP[0], g_hA);
    cudaGetSymbolAddress((void**)&hP[1], g_hB);
    cudaGetSymbolAddress((void**)&rawP[0], g_rawA);
    cudaGetSymbolAddress((void**)&rawP[1], g_rawB);
    cudaGetSymbolAddress((void**)&cntp, g_cnt);

    cudaFuncSetAttribute(k_mm, cudaFuncAttributeMaxDynamicSharedMemorySize, SMEM_MM_TOTAL);

    int dev = 0, sms = 148;
    cudaGetDevice(&dev);
    cudaDeviceGetAttribute(&sms, cudaDevAttrMultiProcessorCount, dev);
    if (sms < 1) sms = 148;

    const int totTiles = (Nn + 127) / 128;               // 391
    int splitT = 2 * sms;                                 // exactly 2 full waves
    if (splitT >= totTiles) splitT = totTiles - 1;
    if (splitT < 1) splitT = 1;
    const int tilesA = splitT, tilesB = totTiles - splitT;
    int nodeSplit = splitT * 128; if (nodeSplit > Nn) nodeSplit = Nn;

    int vblocks = (Nn * 32 + 255) / 256;
    int aBlocksA = (nodeSplit * 32 + 255) / 256;
    int aBlocksB = ((Nn - nodeSplit) * 32 + 255) / 256;
    if (aBlocksB < 1) aBlocksB = 1;

    cudaStream_t s0 = (cudaStream_t)0;   // capture-origin stream (GEMMs)
    cudaStream_t s1;                      // CSR + aggepi
    cudaStreamCreateWithFlags(&s1, cudaStreamNonBlocking);

    cudaEvent_t evFork, evCSR, evMM[4], evAggA[4], evAggB[4];
    cudaEventCreateWithFlags(&evFork, cudaEventDisableTiming);
    cudaEventCreateWithFlags(&evCSR, cudaEventDisableTiming);
    for (int l = 0; l < 4; l++) {
        cudaEventCreateWithFlags(&evMM[l], cudaEventDisableTiming);
        cudaEventCreateWithFlags(&evAggA[l], cudaEventDisableTiming);
        cudaEventCreateWithFlags(&evAggB[l], cudaEventDisableTiming);
    }

    cudaEventRecord(evFork, s0);
    cudaStreamWaitEvent(s1, evFork, 0);

    // submissions: conv(1), count(2), scan(3), mm0(4 = ncu control slot), fill(5), sortseg(6)
    k_conv<<<vblocks, 256, 0, s0>>>(features, W0f, W1f, W0h, W1h, Nn);
    cudaMemsetAsync(cntp, 0, (size_t)Nn * sizeof(int), s1);
    k_count<<<(Ee + 255) / 256, 256, 0, s1>>>(edges, Ee);
    k_scan<<<1, 1024, 0, s1>>>(Nn);
    k_mm<<<totTiles, 512, SMEM_MM_TOTAL, s0>>>(fhi, flo,
        whi + 0 * 2048, wlo + 0 * 2048,
        whi + 1 * 2048, wlo + 1 * 2048,
        hP[0], (float*)rawP[0], 0, Nn);
    cudaEventRecord(evMM[0], s0);
    k_fill<<<(Ee + 255) / 256, 256, 0, s1>>>(edges, Ee);
    k_sortseg<<<(Nn + 127) / 128, 128, 0, s1>>>(Nn);
    cudaEventRecord(evCSR, s1);   // s1 continues; aggepi launches below stay on s1

    for (int l = 0; l < 4; l++) {
        const __half* hrd = hP[l & 1];
        const float4* rrd = rawP[l & 1];
        const float* bb = (l == 0) ? bf : bh + (size_t)(l - 1) * D;
        int mode = (l == 0) ? 0 : (l == 3 ? 2 : 1);

        // aggepi on s1: needs this layer's mm (h/raw) complete
        cudaStreamWaitEvent(s1, evMM[l], 0);
        k_aggepi<<<aBlocksA, 256, 0, s1>>>(hrd, rrd, bb, (const float4*)features,
                                           (float4*)d_out, (uint2*)fhi, (uint2*)flo,
                                           0, nodeSplit, mode);
        cudaEventRecord(evAggA[l], s1);
        k_aggepi<<<aBlocksB, 256, 0, s1>>>(hrd, rrd, bb, (const float4*)features,
                                           (float4*)d_out, (uint2*)fhi, (uint2*)flo,
                                           nodeSplit, Nn, mode);
        cudaEventRecord(evAggB[l], s1);

        if (l < 3) {
            int nl = l + 1;
            __half* hwr = hP[nl & 1];
            float* rwr = (float*)rawP[nl & 1];
            const uint4* W1h_ = whi + (size_t)(2 * nl) * 2048;
            const uint4* W1l_ = wlo + (size_t)(2 * nl) * 2048;
            const uint4* W0h_ = whi + (size_t)(2 * nl + 1) * 2048;
            const uint4* W0l_ = wlo + (size_t)(2 * nl + 1) * 2048;
            // mm part A (2 exact waves) overlaps aggB of this layer
            cudaStreamWaitEvent(s0, evAggA[l], 0);
            k_mm<<<tilesA, 512, SMEM_MM_TOTAL, s0>>>(fhi, flo, W1h_, W1l_, W0h_, W0l_,
                                                     hwr, rwr, 0, Nn);
            cudaStreamWaitEvent(s0, evAggB[l], 0);
            k_mm<<<tilesB, 512, SMEM_MM_TOTAL, s0>>>(fhi, flo, W1h_, W1l_, W0h_, W0l_,
                                                     hwr, rwr, nodeSplit, Nn);
            cudaEventRecord(evMM[nl], s0);
        }
    }

    // join s1 back into the capture-origin stream (final outputs written by aggepi_3)
    cudaStreamWaitEvent(s0, evAggB[3], 0);
}

// round 12
// speedup vs baseline: 1.0808x; 1.0808x over previous
#include <cuda_runtime.h>
#include <cuda_bf16.h>
#include <cuda_fp16.h>
#include <stdint.h>

#define NMAX 50000
#define EMAX 600000
#define D 128

// ======================= device scratch (no allocation) =======================
__device__ uint4  g_fhi4[NMAX * D / 8];       // bf16 hi of layer input
__device__ uint4  g_flo4[NMAX * D / 8];       // bf16 lo
__device__ uint4  g_Whi4[8 * D * D / 8];      // 8 weight matrices bf16 hi [l*2 + {0:W1,1:W0}]
__device__ uint4  g_Wlo4[8 * D * D / 8];
__device__ __half g_h[NMAX * D];              // h = f @ W1^T (fp16 — gather payload)
__device__ float4 g_raw[NMAX * D / 4];        // raw = f @ W0^T (fp32)
__device__ int    g_cnt[NMAX];
__device__ int    g_cursor[NMAX];
__device__ int    g_rowptr[NMAX + 1];
__device__ float  g_invdeg[NMAX];
__device__ int    g_adj[2 * EMAX];            // after sortseg: BYTE offsets (nb*256)

// ======================= bf16 hi/lo split =======================
__device__ __forceinline__ void split4(float4 v, uint2& hi, uint2& lo) {
    __nv_bfloat16 hx = __float2bfloat16_rn(v.x);
    __nv_bfloat16 hy = __float2bfloat16_rn(v.y);
    __nv_bfloat16 hz = __float2bfloat16_rn(v.z);
    __nv_bfloat16 hw = __float2bfloat16_rn(v.w);
    __nv_bfloat16 lx = __float2bfloat16_rn(v.x - __bfloat162float(hx));
    __nv_bfloat16 ly = __float2bfloat16_rn(v.y - __bfloat162float(hy));
    __nv_bfloat16 lz = __float2bfloat16_rn(v.z - __bfloat162float(hz));
    __nv_bfloat16 lw = __float2bfloat16_rn(v.w - __bfloat162float(hw));
    __nv_bfloat162 h01 = __halves2bfloat162(hx, hy);
    __nv_bfloat162 h23 = __halves2bfloat162(hz, hw);
    __nv_bfloat162 l01 = __halves2bfloat162(lx, ly);
    __nv_bfloat162 l23 = __halves2bfloat162(lz, lw);
    hi.x = *(uint32_t*)&h01; hi.y = *(uint32_t*)&h23;
    lo.x = *(uint32_t*)&l01; lo.y = *(uint32_t*)&l23;
}

__global__ void k_conv(const float* __restrict__ features,
                       const float* __restrict__ W0f, const float* __restrict__ W1f,
                       const float* __restrict__ W0h, const float* __restrict__ W1h,
                       int Nn) {
    int i = blockIdx.x * blockDim.x + threadIdx.x;
    if (i < Nn * 32) {
        float4 v = ((const float4*)features)[i];
        uint2 hi, lo;
        split4(v, hi, lo);
        ((uint2*)g_fhi4)[i] = hi;
        ((uint2*)g_flo4)[i] = lo;
    }
    if (i < 8 * 4096) {
        int m = i >> 12;
        int off = i & 4095;
        int l = m >> 1;
        int isW0 = m & 1;
        const float* src = (l == 0) ? (isW0 ? W0f : W1f)
                                    : (isW0 ? W0h + (size_t)(l - 1) * D * D
                                            : W1h + (size_t)(l - 1) * D * D);
        float4 v = ((const float4*)src)[off];
        uint2 hi, lo;
        split4(v, hi, lo);
        ((uint2*)g_Whi4)[(size_t)m * 4096 + off] = hi;
        ((uint2*)g_Wlo4)[(size_t)m * 4096 + off] = lo;
    }
}

// ======================= CSR build =======================
__global__ void k_count(const int* __restrict__ edges, int E) {
    int e = blockIdx.x * blockDim.x + threadIdx.x;
    if (e < E) {
        atomicAdd(&g_cnt[edges[2 * e]], 1);
        atomicAdd(&g_cnt[edges[2 * e + 1]], 1);
    }
}

__global__ void k_scan(int n) {
    __shared__ int ss[1024];
    int t = threadIdx.x;
    int chunk = (n + 1023) >> 10;
    int b = t * chunk;
    int e = min(b + chunk, n);
    int s = 0;
    for (int i = b; i < e; i++) s += g_cnt[i];
    ss[t] = s;
    __syncthreads();
    for (int off = 1; off < 1024; off <<= 1) {
        int add = (t >= off) ? ss[t - off] : 0;
        __syncthreads();
        ss[t] += add;
        __syncthreads();
    }
    int run = (t == 0) ? 0 : ss[t - 1];
    for (int i = b; i < e; i++) {
        g_rowptr[i] = run;
        g_cursor[i] = run;
        int c = g_cnt[i];
        g_invdeg[i] = 1.0f / (float)(c > 0 ? c : 1);
        run += c;
    }
    if (t == 1023) g_rowptr[n] = ss[1023];
}

__global__ void k_fill(const int* __restrict__ edges, int E) {
    int e = blockIdx.x * blockDim.x + threadIdx.x;
    if (e < E) {
        int s = edges[2 * e];
        int d = edges[2 * e + 1];
        g_adj[atomicAdd(&g_cursor[s], 1)] = d;
        g_adj[atomicAdd(&g_cursor[d], 1)] = s;
    }
}

// deterministic adjacency order (sorted) + convert to byte offsets (nb*256)
#define SORT_BUF 96
__global__ void k_sortseg(int n) {
    int i = blockIdx.x * blockDim.x + threadIdx.x;
    if (i >= n) return;
    int b = g_rowptr[i], e = g_rowptr[i + 1];
    int len = e - b;
    if (len <= 0) return;
    if (len <= SORT_BUF) {
        int buf[SORT_BUF];
        for (int j = 0; j < len; j++) buf[j] = g_adj[b + j];
        for (int j = 1; j < len; j++) {
            int key = buf[j];
            int k = j - 1;
            while (k >= 0 && buf[k] > key) { buf[k + 1] = buf[k]; --k; }
            buf[k + 1] = key;
        }
        for (int j = 0; j < len; j++) g_adj[b + j] = buf[j] << 8;   // *256
    } else {
        for (int j = b + 1; j < e; j++) {
            int key = g_adj[j];
            int k = j - 1;
            while (k >= b && g_adj[k] > key) { g_adj[k + 1] = g_adj[k]; --k; }
            g_adj[k + 1] = key;
        }
        for (int j = b; j < e; j++) g_adj[j] <<= 8;
    }
}

// ======================= tensor-core fused GEMM (mma.sync bf16) ================
// R10 interior (unchanged).
#define SROW 272
#define STILE (128 * SROW)
#define SM_A_HI  0
#define SM_A_LO  (STILE)
#define SM_W1HI  (2 * STILE)
#define SM_W1LO  (3 * STILE)
#define SM_W0HI  (4 * STILE)
#define SM_W0LO  (5 * STILE)
#define SMEM_MM_TOTAL (6 * STILE)          // 208896 B

__device__ __forceinline__ uint32_t smem_to_u32(const void* smem_ptr) {
    uint32_t addr;
    asm("{ .reg .u64 tmp; cvta.to.shared.u64 tmp, %1; cvt.u32.u64 %0, tmp; }"
        : "=r"(addr) : "l"(smem_ptr));
    return addr;
}

__device__ __forceinline__ void ldm_x4(uint32_t* r, uint32_t addr) {
    asm volatile("ldmatrix.sync.aligned.m8n8.x4.shared.b16 {%0,%1,%2,%3}, [%4];"
        : "=r"(r[0]), "=r"(r[1]), "=r"(r[2]), "=r"(r[3]) : "r"(addr));
}

__device__ __forceinline__ void mma16816(float* c, const uint32_t* a, const uint32_t* b) {
    asm volatile(
        "mma.sync.aligned.m16n8k16.row.col.f32.bf16.bf16.f32 "
        "{%0,%1,%2,%3}, {%4,%5,%6,%7}, {%8,%9}, {%0,%1,%2,%3};"
        : "+f"(c[0]), "+f"(c[1]), "+f"(c[2]), "+f"(c[3])
        : "r"(a[0]), "r"(a[1]), "r"(a[2]), "r"(a[3]), "r"(b[0]), "r"(b[1]));
}

__global__ void __launch_bounds__(512, 1)
k_mm(const uint4* __restrict__ fhi, const uint4* __restrict__ flo,
     const uint4* __restrict__ w1hi, const uint4* __restrict__ w1lo,
     const uint4* __restrict__ w0hi, const uint4* __restrict__ w0lo,
     __half* __restrict__ hout, float* __restrict__ rawout, int M) {
    extern __shared__ char smem[];
    const int tid = threadIdx.x;
    const int wid = tid >> 5;
    const int lane = tid & 31;
    const int ph = wid >> 3;
    const int w8 = wid & 7;
    const int wm = w8 >> 1;
    const int wn = w8 & 1;
    const int rowBase = blockIdx.x * 128;

    const uint4 z4 = make_uint4(0, 0, 0, 0);
#pragma unroll 4
    for (int i = tid; i < 2048; i += 512) {
        int r = i >> 4, c = i & 15;
        uint32_t off = (uint32_t)r * SROW + (uint32_t)c * 16;
        bool ok = (rowBase + r) < M;
        size_t gi = (size_t)rowBase * 16 + i;
        *(uint4*)(smem + SM_A_HI + off) = ok ? fhi[gi] : z4;
        *(uint4*)(smem + SM_A_LO + off) = ok ? flo[gi] : z4;
        *(uint4*)(smem + SM_W1HI + off) = w1hi[i];
        *(uint4*)(smem + SM_W1LO + off) = w1lo[i];
        *(uint4*)(smem + SM_W0HI + off) = w0hi[i];
        *(uint4*)(smem + SM_W0LO + off) = w0lo[i];
    }
    __syncthreads();

    uint32_t sb = smem_to_u32(smem);
    const uint32_t aRowOff = (uint32_t)(wm * 32 + (lane & 15)) * SROW + ((lane >> 4) << 4);
    const uint32_t bRowCore = (uint32_t)(((lane >> 4) << 3) + (lane & 7)) * SROW
                            + (((lane >> 3) & 1) << 4);
    const int g = lane >> 2, tg = lane & 3;

    uint32_t wHi = sb + (ph ? SM_W0HI : SM_W1HI);
    uint32_t wLo = sb + (ph ? SM_W0LO : SM_W1LO);
    uint32_t aHiB = sb + SM_A_HI, aLoB = sb + SM_A_LO;

    float acc[2][8][4];
#pragma unroll
    for (int mt = 0; mt < 2; mt++)
#pragma unroll
        for (int nt = 0; nt < 8; nt++)
#pragma unroll
            for (int q = 0; q < 4; q++) acc[mt][nt][q] = 0.f;

#pragma unroll 1
    for (int ks = 0; ks < 8; ks++) {
        uint32_t kb = (uint32_t)ks * 32;
        uint32_t aH[2][4], aL[2][4];
        ldm_x4(aH[0], aHiB + aRowOff + kb);
        ldm_x4(aH[1], aHiB + aRowOff + 16 * SROW + kb);
        ldm_x4(aL[0], aLoB + aRowOff + kb);
        ldm_x4(aL[1], aLoB + aRowOff + 16 * SROW + kb);
        uint32_t bH[8][2], bL[8][2];
#pragma unroll
        for (int np = 0; np < 4; np++) {
            uint32_t rowoff = (uint32_t)(wn * 64 + np * 16) * SROW + bRowCore + kb;
            uint32_t tmp[4];
            ldm_x4(tmp, wHi + rowoff);
            bH[np * 2][0] = tmp[0]; bH[np * 2][1] = tmp[1];
            bH[np * 2 + 1][0] = tmp[2]; bH[np * 2 + 1][1] = tmp[3];
            ldm_x4(tmp, wLo + rowoff);
            bL[np * 2][0] = tmp[0]; bL[np * 2][1] = tmp[1];
            bL[np * 2 + 1][0] = tmp[2]; bL[np * 2 + 1][1] = tmp[3];
        }
#pragma unroll
        for (int mt = 0; mt < 2; mt++)
#pragma unroll
            for (int nt = 0; nt < 8; nt++) {
                mma16816(acc[mt][nt], aH[mt], bH[nt]);   // hi*hi
                mma16816(acc[mt][nt], aH[mt], bL[nt]);   // hi*lo
                mma16816(acc[mt][nt], aL[mt], bH[nt]);   // lo*hi
            }
    }

#pragma unroll
    for (int mt = 0; mt < 2; mt++) {
        int row0 = rowBase + wm * 32 + mt * 16 + g;
#pragma unroll
        for (int nt = 0; nt < 8; nt++) {
            int col = wn * 64 + nt * 8 + tg * 2;
            if (ph == 0) {
                if (row0 < M)
                    *(__half2*)(hout + (size_t)row0 * 128 + col) =
                        __floats2half2_rn(acc[mt][nt][0], acc[mt][nt][1]);
                if (row0 + 8 < M)
                    *(__half2*)(hout + (size_t)(row0 + 8) * 128 + col) =
                        __floats2half2_rn(acc[mt][nt][2], acc[mt][nt][3]);
            } else {
                if (row0 < M)
                    *(float2*)(rawout + (size_t)row0 * 128 + col) =
                        make_float2(acc[mt][nt][0], acc[mt][nt][1]);
                if (row0 + 8 < M)
                    *(float2*)(rawout + (size_t)(row0 + 8) * 128 + col) =
                        make_float2(acc[mt][nt][2], acc[mt][nt][3]);
            }
        }
    }
}

// ============ fused aggregate + epilogue: 64-thread blocks (2 warps = 2 nodes) ============
// Small blocks retire independently -> degree-skew tail no longer holds 8 warps hostage.
__global__ void __launch_bounds__(64)
k_aggepi(const __half* __restrict__ h, const float4* __restrict__ raw,
         const float* __restrict__ bias, const float4* __restrict__ res,
         float4* __restrict__ outF,
         uint2* __restrict__ fhi, uint2* __restrict__ flo,
         int n, int mode) {
    int node = (blockIdx.x * blockDim.x + threadIdx.x) >> 5;
    if (node >= n) return;
    int lane = threadIdx.x & 31;
    int b = g_rowptr[node], e = g_rowptr[node + 1];
    const char* hb = (const char*)h;

    float4 acc[8];
#pragma unroll
    for (int q = 0; q < 8; q++) acc[q] = make_float4(0.f, 0.f, 0.f, 0.f);

    int p = b;
    for (; p + 8 <= e; p += 8) {
        int off[8];
#pragma unroll
        for (int q = 0; q < 8; q++) off[q] = g_adj[p + q];   // byte offsets
        uint2 u[8];
#pragma unroll
        for (int q = 0; q < 8; q++)
            u[q] = __ldcg((const uint2*)(hb + off[q]) + lane);
#pragma unroll
        for (int q = 0; q < 8; q++) {
            float2 x = __half22float2(*(__half2*)&u[q].x);
            float2 y = __half22float2(*(__half2*)&u[q].y);
            acc[q].x += x.x; acc[q].y += x.y; acc[q].z += y.x; acc[q].w += y.y;
        }
    }
    if (p + 4 <= e) {
        int off[4];
#pragma unroll
        for (int q = 0; q < 4; q++) off[q] = g_adj[p + q];
#pragma unroll
        for (int q = 0; q < 4; q++) {
            uint2 u = __ldcg((const uint2*)(hb + off[q]) + lane);
            float2 x = __half22float2(*(__half2*)&u.x);
            float2 y = __half22float2(*(__half2*)&u.y);
            acc[q].x += x.x; acc[q].y += x.y; acc[q].z += y.x; acc[q].w += y.y;
        }
        p += 4;
    }
    for (; p < e; ++p) {
        uint2 u = __ldcg((const uint2*)(hb + g_adj[p]) + lane);
        float2 x = __half22float2(*(__half2*)&u.x);
        float2 y = __half22float2(*(__half2*)&u.y);
        acc[0].x += x.x; acc[0].y += x.y; acc[0].z += y.x; acc[0].w += y.y;
    }

    // fixed pairwise tree (deterministic across replays)
    float4 s01, s23, s45, s67, sA, sB, sum;
    s01.x = acc[0].x + acc[1].x; s01.y = acc[0].y + acc[1].y; s01.z = acc[0].z + acc[1].z; s01.w = acc[0].w + acc[1].w;
    s23.x = acc[2].x + acc[3].x; s23.y = acc[2].y + acc[3].y; s23.z = acc[2].z + acc[3].z; s23.w = acc[2].w + acc[3].w;
    s45.x = acc[4].x + acc[5].x; s45.y = acc[4].y + acc[5].y; s45.z = acc[4].z + acc[5].z; s45.w = acc[4].w + acc[5].w;
    s67.x = acc[6].x + acc[7].x; s67.y = acc[6].y + acc[7].y; s67.z = acc[6].z + acc[7].z; s67.w = acc[6].w + acc[7].w;
    sA.x = s01.x + s23.x; sA.y = s01.y + s23.y; sA.z = s01.z + s23.z; sA.w = s01.w + s23.w;
    sB.x = s45.x + s67.x; sB.y = s45.y + s67.y; sB.z = s45.z + s67.z; sB.w = s45.w + s67.w;
    sum.x = sA.x + sB.x; sum.y = sA.y + sB.y; sum.z = sA.z + sB.z; sum.w = sA.w + sB.w;

    float s = g_invdeg[node];
    size_t idx = (size_t)node * 32 + lane;
    float4 v = raw[idx];
    float4 bb = ((const float4*)bias)[lane];
    v.x += bb.x + sum.x * s;
    v.y += bb.y + sum.y * s;
    v.z += bb.z + sum.z * s;
    v.w += bb.w + sum.w * s;
    if (mode == 2) {
        float4 r = res[idx];
        v.x += r.x; v.y += r.y; v.z += r.z; v.w += r.w;
    }
    if (mode >= 1) {
        v.x = fmaxf(v.x, 0.f); v.y = fmaxf(v.y, 0.f);
        v.z = fmaxf(v.z, 0.f); v.w = fmaxf(v.w, 0.f);
    }
    if (mode == 2) {
        outF[idx] = v;
    } else {
        uint2 hi, lo;
        split4(v, hi, lo);
        fhi[idx] = hi;
        flo[idx] = lo;
    }
}

// ======================= launch =======================
extern "C" void kernel_launch(void* const* d_in, const int* in_sizes, int n_in,
                              void* d_out, int out_size) {
    const float* features = (const float*)d_in[0];
    const int*   edges    = (const int*)d_in[1];
    const float* W0f = (const float*)d_in[3];
    const float* W1f = (const float*)d_in[4];
    const float* bf  = (const float*)d_in[5];
    const float* W0h = (const float*)d_in[6];
    const float* W1h = (const float*)d_in[7];
    const float* bh  = (const float*)d_in[8];

    int Nn = in_sizes[0] / D;
    int Ee = in_sizes[1] / 2;

    uint4 *fhi, *flo, *whi, *wlo;
    __half* hbuf;
    float4* rawb;
    int* cntp;
    cudaGetSymbolAddress((void**)&fhi, g_fhi4);
    cudaGetSymbolAddress((void**)&flo, g_flo4);
    cudaGetSymbolAddress((void**)&whi, g_Whi4);
    cudaGetSymbolAddress((void**)&wlo, g_Wlo4);
    cudaGetSymbolAddress((void**)&hbuf, g_h);
    cudaGetSymbolAddress((void**)&rawb, g_raw);
    cudaGetSymbolAddress((void**)&cntp, g_cnt);

    cudaFuncSetAttribute(k_mm, cudaFuncAttributeMaxDynamicSharedMemorySize, SMEM_MM_TOTAL);

    int vblocks = (Nn * 32 + 255) / 256;
    int gblocks = (Nn + 127) / 128;
    int ablocks = (Nn * 32 + 63) / 64;     // 64-thread blocks, 2 nodes each

    cudaStream_t s0 = (cudaStream_t)0;   // capture-origin stream
    cudaStream_t s1;
    cudaStreamCreateWithFlags(&s1, cudaStreamNonBlocking);

    cudaEvent_t evFork, evCSR;
    cudaEventCreateWithFlags(&evFork, cudaEventDisableTiming);
    cudaEventCreateWithFlags(&evCSR, cudaEventDisableTiming);

    cudaEventRecord(evFork, s0);
    cudaStreamWaitEvent(s1, evFork, 0);

    // s0: conv -> mm0 (serial); s1: CSR chain, overlapped
    k_conv<<<vblocks, 256, 0, s0>>>(features, W0f, W1f, W0h, W1h, Nn);
    cudaMemsetAsync(cntp, 0, (size_t)Nn * sizeof(int), s1);
    k_count<<<(Ee + 255) / 256, 256, 0, s1>>>(edges, Ee);
    k_scan<<<1, 1024, 0, s1>>>(Nn);
    k_mm<<<gblocks, 512, SMEM_MM_TOTAL, s0>>>(fhi, flo,
        whi + 0 * 2048, wlo + 0 * 2048,
        whi + 1 * 2048, wlo + 1 * 2048,
        hbuf, (float*)rawb, Nn);
    k_fill<<<(Ee + 255) / 256, 256, 0, s1>>>(edges, Ee);
    k_sortseg<<<(Nn + 127) / 128, 128, 0, s1>>>(Nn);
    cudaEventRecord(evCSR, s1);
    cudaStreamWaitEvent(s0, evCSR, 0);   // join: aggepi needs the CSR

    for (int l = 0; l < 4; l++) {
        if (l > 0) {
            k_mm<<<gblocks, 512, SMEM_MM_TOTAL, s0>>>(fhi, flo,
                whi + (size_t)(2 * l) * 2048,     wlo + (size_t)(2 * l) * 2048,
                whi + (size_t)(2 * l + 1) * 2048, wlo + (size_t)(2 * l + 1) * 2048,
                hbuf, (float*)rawb, Nn);
        }
        const float* bb = (l == 0) ? bf : bh + (size_t)(l - 1) * D;
        int mode = (l == 0) ? 0 : (l == 3 ? 2 : 1);
        k_aggepi<<<ablocks, 64, 0, s0>>>(hbuf, rawb, bb, (const float4*)features,
                                         (float4*)d_out, (uint2*)fhi, (uint2*)flo,
                                         Nn, mode);
    }
}

// round 13
// speedup vs baseline: 1.0997x; 1.0174x over previous
#include <cuda_runtime.h>
#include <cuda_bf16.h>
#include <cuda_fp16.h>
#include <stdint.h>

#define NMAX 50000
#define EMAX 600000
#define D 128

// ======================= device scratch (no allocation) =======================
__device__ uint4  g_fhi4[NMAX * D / 8];       // bf16 hi of layer input
__device__ uint4  g_flo4[NMAX * D / 8];       // bf16 lo
__device__ uint4  g_Whi4[8 * D * D / 8];      // 8 weight matrices bf16 hi [l*2 + {0:W1,1:W0}]
__device__ uint4  g_Wlo4[8 * D * D / 8];
__device__ __half g_h[NMAX * D];              // h = f @ W1^T (fp16 — gather payload)
__device__ float4 g_raw[NMAX * D / 4];        // raw = f @ W0^T (fp32)
__device__ int    g_cnt[NMAX];
__device__ int    g_cursor[NMAX];
__device__ int    g_rowptr[NMAX + 1];
__device__ float  g_invdeg[NMAX];
__device__ int    g_adj[2 * EMAX];            // after sortseg: BYTE offsets (nb*256)

// ======================= bf16 hi/lo split =======================
__device__ __forceinline__ void split4(float4 v, uint2& hi, uint2& lo) {
    __nv_bfloat16 hx = __float2bfloat16_rn(v.x);
    __nv_bfloat16 hy = __float2bfloat16_rn(v.y);
    __nv_bfloat16 hz = __float2bfloat16_rn(v.z);
    __nv_bfloat16 hw = __float2bfloat16_rn(v.w);
    __nv_bfloat16 lx = __float2bfloat16_rn(v.x - __bfloat162float(hx));
    __nv_bfloat16 ly = __float2bfloat16_rn(v.y - __bfloat162float(hy));
    __nv_bfloat16 lz = __float2bfloat16_rn(v.z - __bfloat162float(hz));
    __nv_bfloat16 lw = __float2bfloat16_rn(v.w - __bfloat162float(hw));
    __nv_bfloat162 h01 = __halves2bfloat162(hx, hy);
    __nv_bfloat162 h23 = __halves2bfloat162(hz, hw);
    __nv_bfloat162 l01 = __halves2bfloat162(lx, ly);
    __nv_bfloat162 l23 = __halves2bfloat162(lz, lw);
    hi.x = *(uint32_t*)&h01; hi.y = *(uint32_t*)&h23;
    lo.x = *(uint32_t*)&l01; lo.y = *(uint32_t*)&l23;
}

__global__ void k_conv(const float* __restrict__ features,
                       const float* __restrict__ W0f, const float* __restrict__ W1f,
                       const float* __restrict__ W0h, const float* __restrict__ W1h,
                       int Nn) {
    int i = blockIdx.x * blockDim.x + threadIdx.x;
    if (i < Nn * 32) {
        float4 v = ((const float4*)features)[i];
        uint2 hi, lo;
        split4(v, hi, lo);
        ((uint2*)g_fhi4)[i] = hi;
        ((uint2*)g_flo4)[i] = lo;
    }
    if (i < 8 * 4096) {
        int m = i >> 12;
        int off = i & 4095;
        int l = m >> 1;
        int isW0 = m & 1;
        const float* src = (l == 0) ? (isW0 ? W0f : W1f)
                                    : (isW0 ? W0h + (size_t)(l - 1) * D * D
                                            : W1h + (size_t)(l - 1) * D * D);
        float4 v = ((const float4*)src)[off];
        uint2 hi, lo;
        split4(v, hi, lo);
        ((uint2*)g_Whi4)[(size_t)m * 4096 + off] = hi;
        ((uint2*)g_Wlo4)[(size_t)m * 4096 + off] = lo;
    }
}

// ======================= CSR build =======================
__global__ void k_count(const int* __restrict__ edges, int E) {
    int e = blockIdx.x * blockDim.x + threadIdx.x;
    if (e < E) {
        atomicAdd(&g_cnt[edges[2 * e]], 1);
        atomicAdd(&g_cnt[edges[2 * e + 1]], 1);
    }
}

__global__ void k_scan(int n) {
    __shared__ int ss[1024];
    int t = threadIdx.x;
    int chunk = (n + 1023) >> 10;
    int b = t * chunk;
    int e = min(b + chunk, n);
    int s = 0;
    for (int i = b; i < e; i++) s += g_cnt[i];
    ss[t] = s;
    __syncthreads();
    for (int off = 1; off < 1024; off <<= 1) {
        int add = (t >= off) ? ss[t - off] : 0;
        __syncthreads();
        ss[t] += add;
        __syncthreads();
    }
    int run = (t == 0) ? 0 : ss[t - 1];
    for (int i = b; i < e; i++) {
        g_rowptr[i] = run;
        g_cursor[i] = run;
        int c = g_cnt[i];
        g_invdeg[i] = 1.0f / (float)(c > 0 ? c : 1);
        run += c;
    }
    if (t == 1023) g_rowptr[n] = ss[1023];
}

__global__ void k_fill(const int* __restrict__ edges, int E) {
    int e = blockIdx.x * blockDim.x + threadIdx.x;
    if (e < E) {
        int s = edges[2 * e];
        int d = edges[2 * e + 1];
        g_adj[atomicAdd(&g_cursor[s], 1)] = d;
        g_adj[atomicAdd(&g_cursor[d], 1)] = s;
    }
}

// deterministic adjacency order (sorted) + convert to byte offsets (nb*256)
#define SORT_BUF 96
__global__ void k_sortseg(int n) {
    int i = blockIdx.x * blockDim.x + threadIdx.x;
    if (i >= n) return;
    int b = g_rowptr[i], e = g_rowptr[i + 1];
    int len = e - b;
    if (len <= 0) return;
    if (len <= SORT_BUF) {
        int buf[SORT_BUF];
        for (int j = 0; j < len; j++) buf[j] = g_adj[b + j];
        for (int j = 1; j < len; j++) {
            int key = buf[j];
            int k = j - 1;
            while (k >= 0 && buf[k] > key) { buf[k + 1] = buf[k]; --k; }
            buf[k + 1] = key;
        }
        for (int j = 0; j < len; j++) g_adj[b + j] = buf[j] << 8;   // *256
    } else {
        for (int j = b + 1; j < e; j++) {
            int key = g_adj[j];
            int k = j - 1;
            while (k >= b && g_adj[k] > key) { g_adj[k + 1] = g_adj[k]; --k; }
            g_adj[k + 1] = key;
        }
        for (int j = b; j < e; j++) g_adj[j] <<= 8;
    }
}

// ======================= tensor-core fused GEMM (mma.sync bf16) ================
// R10/R12 interior (unchanged control).
#define SROW 272
#define STILE (128 * SROW)
#define SM_A_HI  0
#define SM_A_LO  (STILE)
#define SM_W1HI  (2 * STILE)
#define SM_W1LO  (3 * STILE)
#define SM_W0HI  (4 * STILE)
#define SM_W0LO  (5 * STILE)
#define SMEM_MM_TOTAL (6 * STILE)          // 208896 B

__device__ __forceinline__ uint32_t smem_to_u32(const void* smem_ptr) {
    uint32_t addr;
    asm("{ .reg .u64 tmp; cvta.to.shared.u64 tmp, %1; cvt.u32.u64 %0, tmp; }"
        : "=r"(addr) : "l"(smem_ptr));
    return addr;
}

__device__ __forceinline__ void ldm_x4(uint32_t* r, uint32_t addr) {
    asm volatile("ldmatrix.sync.aligned.m8n8.x4.shared.b16 {%0,%1,%2,%3}, [%4];"
        : "=r"(r[0]), "=r"(r[1]), "=r"(r[2]), "=r"(r[3]) : "r"(addr));
}

__device__ __forceinline__ void mma16816(float* c, const uint32_t* a, const uint32_t* b) {
    asm volatile(
        "mma.sync.aligned.m16n8k16.row.col.f32.bf16.bf16.f32 "
        "{%0,%1,%2,%3}, {%4,%5,%6,%7}, {%8,%9}, {%0,%1,%2,%3};"
        : "+f"(c[0]), "+f"(c[1]), "+f"(c[2]), "+f"(c[3])
        : "r"(a[0]), "r"(a[1]), "r"(a[2]), "r"(a[3]), "r"(b[0]), "r"(b[1]));
}

__global__ void __launch_bounds__(512, 1)
k_mm(const uint4* __restrict__ fhi, const uint4* __restrict__ flo,
     const uint4* __restrict__ w1hi, const uint4* __restrict__ w1lo,
     const uint4* __restrict__ w0hi, const uint4* __restrict__ w0lo,
     __half* __restrict__ hout, float* __restrict__ rawout, int M) {
    extern __shared__ char smem[];
    const int tid = threadIdx.x;
    const int wid = tid >> 5;
    const int lane = tid & 31;
    const int ph = wid >> 3;
    const int w8 = wid & 7;
    const int wm = w8 >> 1;
    const int wn = w8 & 1;
    const int rowBase = blockIdx.x * 128;

    const uint4 z4 = make_uint4(0, 0, 0, 0);
#pragma unroll 4
    for (int i = tid; i < 2048; i += 512) {
        int r = i >> 4, c = i & 15;
        uint32_t off = (uint32_t)r * SROW + (uint32_t)c * 16;
        bool ok = (rowBase + r) < M;
        size_t gi = (size_t)rowBase * 16 + i;
        *(uint4*)(smem + SM_A_HI + off) = ok ? fhi[gi] : z4;
        *(uint4*)(smem + SM_A_LO + off) = ok ? flo[gi] : z4;
        *(uint4*)(smem + SM_W1HI + off) = w1hi[i];
        *(uint4*)(smem + SM_W1LO + off) = w1lo[i];
        *(uint4*)(smem + SM_W0HI + off) = w0hi[i];
        *(uint4*)(smem + SM_W0LO + off) = w0lo[i];
    }
    __syncthreads();

    uint32_t sb = smem_to_u32(smem);
    const uint32_t aRowOff = (uint32_t)(wm * 32 + (lane & 15)) * SROW + ((lane >> 4) << 4);
    const uint32_t bRowCore = (uint32_t)(((lane >> 4) << 3) + (lane & 7)) * SROW
                            + (((lane >> 3) & 1) << 4);
    const int g = lane >> 2, tg = lane & 3;

    uint32_t wHi = sb + (ph ? SM_W0HI : SM_W1HI);
    uint32_t wLo = sb + (ph ? SM_W0LO : SM_W1LO);
    uint32_t aHiB = sb + SM_A_HI, aLoB = sb + SM_A_LO;

    float acc[2][8][4];
#pragma unroll
    for (int mt = 0; mt < 2; mt++)
#pragma unroll
        for (int nt = 0; nt < 8; nt++)
#pragma unroll
            for (int q = 0; q < 4; q++) acc[mt][nt][q] = 0.f;

#pragma unroll 1
    for (int ks = 0; ks < 8; ks++) {
        uint32_t kb = (uint32_t)ks * 32;
        uint32_t aH[2][4], aL[2][4];
        ldm_x4(aH[0], aHiB + aRowOff + kb);
        ldm_x4(aH[1], aHiB + aRowOff + 16 * SROW + kb);
        ldm_x4(aL[0], aLoB + aRowOff + kb);
        ldm_x4(aL[1], aLoB + aRowOff + 16 * SROW + kb);
        uint32_t bH[8][2], bL[8][2];
#pragma unroll
        for (int np = 0; np < 4; np++) {
            uint32_t rowoff = (uint32_t)(wn * 64 + np * 16) * SROW + bRowCore + kb;
            uint32_t tmp[4];
            ldm_x4(tmp, wHi + rowoff);
            bH[np * 2][0] = tmp[0]; bH[np * 2][1] = tmp[1];
            bH[np * 2 + 1][0] = tmp[2]; bH[np * 2 + 1][1] = tmp[3];
            ldm_x4(tmp, wLo + rowoff);
            bL[np * 2][0] = tmp[0]; bL[np * 2][1] = tmp[1];
            bL[np * 2 + 1][0] = tmp[2]; bL[np * 2 + 1][1] = tmp[3];
        }
#pragma unroll
        for (int mt = 0; mt < 2; mt++)
#pragma unroll
            for (int nt = 0; nt < 8; nt++) {
                mma16816(acc[mt][nt], aH[mt], bH[nt]);   // hi*hi
                mma16816(acc[mt][nt], aH[mt], bL[nt]);   // hi*lo
                mma16816(acc[mt][nt], aL[mt], bH[nt]);   // lo*hi
            }
    }

#pragma unroll
    for (int mt = 0; mt < 2; mt++) {
        int row0 = rowBase + wm * 32 + mt * 16 + g;
#pragma unroll
        for (int nt = 0; nt < 8; nt++) {
            int col = wn * 64 + nt * 8 + tg * 2;
            if (ph == 0) {
                if (row0 < M)
                    *(__half2*)(hout + (size_t)row0 * 128 + col) =
                        __floats2half2_rn(acc[mt][nt][0], acc[mt][nt][1]);
                if (row0 + 8 < M)
                    *(__half2*)(hout + (size_t)(row0 + 8) * 128 + col) =
                        __floats2half2_rn(acc[mt][nt][2], acc[mt][nt][3]);
            } else {
                if (row0 < M)
                    *(float2*)(rawout + (size_t)row0 * 128 + col) =
                        make_float2(acc[mt][nt][0], acc[mt][nt][1]);
                if (row0 + 8 < M)
                    *(float2*)(rawout + (size_t)(row0 + 8) * 128 + col) =
                        make_float2(acc[mt][nt][2], acc[mt][nt][3]);
            }
        }
    }
}

// ============ fused aggregate + epilogue: LDG.128 half-warp gathers ============
// One warp per node; one LDG.128 covers TWO neighbor rows (lanes 0-15 -> even-
// stream neighbor, lanes 16-31 -> odd-stream). Lane owns 8 columns (16B chunk).
// Main loop: 8 LDG.128 in flight = 4 KB/warp (2x round-12 bytes in flight).
__device__ __forceinline__ void addu4(float* a, uint4 u) {
    float2 t;
    t = __half22float2(*(__half2*)&u.x); a[0] += t.x; a[1] += t.y;
    t = __half22float2(*(__half2*)&u.y); a[2] += t.x; a[3] += t.y;
    t = __half22float2(*(__half2*)&u.z); a[4] += t.x; a[5] += t.y;
    t = __half22float2(*(__half2*)&u.w); a[6] += t.x; a[7] += t.y;
}

__global__ void __launch_bounds__(64)
k_aggepi(const __half* __restrict__ h, const float4* __restrict__ raw,
         const float* __restrict__ bias, const float4* __restrict__ res,
         float4* __restrict__ outF,
         uint2* __restrict__ fhi, uint2* __restrict__ flo,
         int n, int mode) {
    int node = (blockIdx.x * blockDim.x + threadIdx.x) >> 5;
    if (node >= n) return;
    const int lane = threadIdx.x & 31;
    const int half = lane >> 4;     // 0: even-stream neighbor, 1: odd-stream
    const int ci = lane & 15;       // 16B chunk (8 fp16 columns) within the 256B row
    int b = g_rowptr[node], e = g_rowptr[node + 1];
    const char* hb = (const char*)h;

    float acc0[8], acc1[8];
#pragma unroll
    for (int j = 0; j < 8; j++) { acc0[j] = 0.f; acc1[j] = 0.f; }

    int p = b;
    // 16 neighbors per iteration: 8 LDG.128, each serving 2 rows
    for (; p + 16 <= e; p += 16) {
        uint4 u[8];
#pragma unroll
        for (int q = 0; q < 8; q++) {
            int off = g_adj[p + 2 * q + half];          // byte offset
            u[q] = __ldcg((const uint4*)(hb + off) + ci);
        }
#pragma unroll
        for (int q = 0; q < 8; q++) addu4((q & 1) ? acc1 : acc0, u[q]);
    }
    if (p + 8 <= e) {
        uint4 u[4];
#pragma unroll
        for (int q = 0; q < 4; q++) {
            int off = g_adj[p + 2 * q + half];
            u[q] = __ldcg((const uint4*)(hb + off) + ci);
        }
#pragma unroll
        for (int q = 0; q < 4; q++) addu4((q & 1) ? acc1 : acc0, u[q]);
        p += 8;
    }
    // remainder pairs (odd tail: half=1 lanes skip)
    for (; p < e; p += 2) {
        int idx = p + half;
        if (idx < e) {
            int off = g_adj[idx];
            uint4 u = __ldcg((const uint4*)(hb + off) + ci);
            addu4(acc0, u);
        }
    }

    // merge streams within lane, then across half-warps (fixed order, deterministic)
    float tot[8];
#pragma unroll
    for (int j = 0; j < 8; j++) tot[j] = acc0[j] + acc1[j];
#pragma unroll
    for (int j = 0; j < 8; j++)
        tot[j] += __shfl_xor_sync(0xffffffffu, tot[j], 16);

    if (half == 0) {
        float s = g_invdeg[node];
        size_t idx = (size_t)node * 32 + (size_t)ci * 2;   // 2 float4 per lane
#pragma unroll
        for (int k = 0; k < 2; k++) {
            float4 v = raw[idx + k];
            float4 bb = ((const float4*)bias)[ci * 2 + k];
            v.x += bb.x + tot[4 * k + 0] * s;
            v.y += bb.y + tot[4 * k + 1] * s;
            v.z += bb.z + tot[4 * k + 2] * s;
            v.w += bb.w + tot[4 * k + 3] * s;
            if (mode == 2) {
                float4 r = res[idx + k];
                v.x += r.x; v.y += r.y; v.z += r.z; v.w += r.w;
            }
            if (mode >= 1) {
                v.x = fmaxf(v.x, 0.f); v.y = fmaxf(v.y, 0.f);
                v.z = fmaxf(v.z, 0.f); v.w = fmaxf(v.w, 0.f);
            }
            if (mode == 2) {
                outF[idx + k] = v;
            } else {
                uint2 hi, lo;
                split4(v, hi, lo);
                fhi[idx + k] = hi;
                flo[idx + k] = lo;
            }
        }
    }
}

// ======================= launch =======================
extern "C" void kernel_launch(void* const* d_in, const int* in_sizes, int n_in,
                              void* d_out, int out_size) {
    const float* features = (const float*)d_in[0];
    const int*   edges    = (const int*)d_in[1];
    const float* W0f = (const float*)d_in[3];
    const float* W1f = (const float*)d_in[4];
    const float* bf  = (const float*)d_in[5];
    const float* W0h = (const float*)d_in[6];
    const float* W1h = (const float*)d_in[7];
    const float* bh  = (const float*)d_in[8];

    int Nn = in_sizes[0] / D;
    int Ee = in_sizes[1] / 2;

    uint4 *fhi, *flo, *whi, *wlo;
    __half* hbuf;
    float4* rawb;
    int* cntp;
    cudaGetSymbolAddress((void**)&fhi, g_fhi4);
    cudaGetSymbolAddress((void**)&flo, g_flo4);
    cudaGetSymbolAddress((void**)&whi, g_Whi4);
    cudaGetSymbolAddress((void**)&wlo, g_Wlo4);
    cudaGetSymbolAddress((void**)&hbuf, g_h);
    cudaGetSymbolAddress((void**)&rawb, g_raw);
    cudaGetSymbolAddress((void**)&cntp, g_cnt);

    cudaFuncSetAttribute(k_mm, cudaFuncAttributeMaxDynamicSharedMemorySize, SMEM_MM_TOTAL);

    int vblocks = (Nn * 32 + 255) / 256;
    int gblocks = (Nn + 127) / 128;
    int ablocks = (Nn * 32 + 63) / 64;     // 64-thread blocks, 2 nodes each

    cudaStream_t s0 = (cudaStream_t)0;   // capture-origin stream
    cudaStream_t s1;
    cudaStreamCreateWithFlags(&s1, cudaStreamNonBlocking);

    cudaEvent_t evFork, evCSR;
    cudaEventCreateWithFlags(&evFork, cudaEventDisableTiming);
    cudaEventCreateWithFlags(&evCSR, cudaEventDisableTiming);

    cudaEventRecord(evFork, s0);
    cudaStreamWaitEvent(s1, evFork, 0);

    // s0: conv -> mm0 (serial); s1: CSR chain, overlapped
    k_conv<<<vblocks, 256, 0, s0>>>(features, W0f, W1f, W0h, W1h, Nn);
    cudaMemsetAsync(cntp, 0, (size_t)Nn * sizeof(int), s1);
    k_count<<<(Ee + 255) / 256, 256, 0, s1>>>(edges, Ee);
    k_scan<<<1, 1024, 0, s1>>>(Nn);
    k_mm<<<gblocks, 512, SMEM_MM_TOTAL, s0>>>(fhi, flo,
        whi + 0 * 2048, wlo + 0 * 2048,
        whi + 1 * 2048, wlo + 1 * 2048,
        hbuf, (float*)rawb, Nn);
    k_fill<<<(Ee + 255) / 256, 256, 0, s1>>>(edges, Ee);
    k_sortseg<<<(Nn + 127) / 128, 128, 0, s1>>>(Nn);
    cudaEventRecord(evCSR, s1);
    cudaStreamWaitEvent(s0, evCSR, 0);   // join: aggepi needs the CSR

    for (int l = 0; l < 4; l++) {
        if (l > 0) {
            k_mm<<<gblocks, 512, SMEM_MM_TOTAL, s0>>>(fhi, flo,
                whi + (size_t)(2 * l) * 2048,     wlo + (size_t)(2 * l) * 2048,
                whi + (size_t)(2 * l + 1) * 2048, wlo + (size_t)(2 * l + 1) * 2048,
                hbuf, (float*)rawb, Nn);
        }
        const float* bb = (l == 0) ? bf : bh + (size_t)(l - 1) * D;
        int mode = (l == 0) ? 0 : (l == 3 ? 2 : 1);
        k_aggepi<<<ablocks, 64, 0, s0>>>(hbuf, rawb, bb, (const float4*)features,
                                         (float4*)d_out, (uint2*)fhi, (uint2*)flo,
                                         Nn, mode);
    }
}

// round 14
// speedup vs baseline: 1.1286x; 1.0262x over previous
#include <cuda_runtime.h>
#include <cuda_bf16.h>
#include <cuda_fp16.h>
#include <stdint.h>

#define NMAX 50000
#define EMAX 600000
#define D 128

// ======================= device scratch (no allocation) =======================
__device__ uint4  g_fhi4[NMAX * D / 8];       // bf16 hi of layer input
__device__ uint4  g_flo4[NMAX * D / 8];       // bf16 lo
__device__ uint4  g_Whi4[8 * D * D / 8];      // 8 weight matrices bf16 hi [l*2 + {0:W1,1:W0}]
__device__ uint4  g_Wlo4[8 * D * D / 8];
__device__ __half g_h[NMAX * D];              // h = f @ W1^T (fp16 — gather payload)
__device__ float4 g_raw[NMAX * D / 4];        // raw = f @ W0^T (fp32)
__device__ int    g_cnt[NMAX];
__device__ int    g_cursor[NMAX];
__device__ int    g_rowptr[NMAX + 1];
__device__ float  g_invdeg[NMAX];
__device__ int    g_adj[2 * EMAX];            // after sortseg: BYTE offsets (nb*256)

// ======================= bf16 hi/lo split =======================
__device__ __forceinline__ void split4(float4 v, uint2& hi, uint2& lo) {
    __nv_bfloat16 hx = __float2bfloat16_rn(v.x);
    __nv_bfloat16 hy = __float2bfloat16_rn(v.y);
    __nv_bfloat16 hz = __float2bfloat16_rn(v.z);
    __nv_bfloat16 hw = __float2bfloat16_rn(v.w);
    __nv_bfloat16 lx = __float2bfloat16_rn(v.x - __bfloat162float(hx));
    __nv_bfloat16 ly = __float2bfloat16_rn(v.y - __bfloat162float(hy));
    __nv_bfloat16 lz = __float2bfloat16_rn(v.z - __bfloat162float(hz));
    __nv_bfloat16 lw = __float2bfloat16_rn(v.w - __bfloat162float(hw));
    __nv_bfloat162 h01 = __halves2bfloat162(hx, hy);
    __nv_bfloat162 h23 = __halves2bfloat162(hz, hw);
    __nv_bfloat162 l01 = __halves2bfloat162(lx, ly);
    __nv_bfloat162 l23 = __halves2bfloat162(lz, lw);
    hi.x = *(uint32_t*)&h01; hi.y = *(uint32_t*)&h23;
    lo.x = *(uint32_t*)&l01; lo.y = *(uint32_t*)&l23;
}

__global__ void k_conv(const float* __restrict__ features,
                       const float* __restrict__ W0f, const float* __restrict__ W1f,
                       const float* __restrict__ W0h, const float* __restrict__ W1h,
                       int Nn) {
    int i = blockIdx.x * blockDim.x + threadIdx.x;
    if (i < Nn * 32) {
        float4 v = ((const float4*)features)[i];
        uint2 hi, lo;
        split4(v, hi, lo);
        ((uint2*)g_fhi4)[i] = hi;
        ((uint2*)g_flo4)[i] = lo;
    }
    if (i < 8 * 4096) {
        int m = i >> 12;
        int off = i & 4095;
        int l = m >> 1;
        int isW0 = m & 1;
        const float* src = (l == 0) ? (isW0 ? W0f : W1f)
                                    : (isW0 ? W0h + (size_t)(l - 1) * D * D
                                            : W1h + (size_t)(l - 1) * D * D);
        float4 v = ((const float4*)src)[off];
        uint2 hi, lo;
        split4(v, hi, lo);
        ((uint2*)g_Whi4)[(size_t)m * 4096 + off] = hi;
        ((uint2*)g_Wlo4)[(size_t)m * 4096 + off] = lo;
    }
}

// ======================= CSR build =======================
__global__ void k_count(const int* __restrict__ edges, int E) {
    int e = blockIdx.x * blockDim.x + threadIdx.x;
    if (e < E) {
        atomicAdd(&g_cnt[edges[2 * e]], 1);
        atomicAdd(&g_cnt[edges[2 * e + 1]], 1);
    }
}

__global__ void k_scan(int n) {
    __shared__ int ss[1024];
    int t = threadIdx.x;
    int chunk = (n + 1023) >> 10;
    int b = t * chunk;
    int e = min(b + chunk, n);
    int s = 0;
    for (int i = b; i < e; i++) s += g_cnt[i];
    ss[t] = s;
    __syncthreads();
    for (int off = 1; off < 1024; off <<= 1) {
        int add = (t >= off) ? ss[t - off] : 0;
        __syncthreads();
        ss[t] += add;
        __syncthreads();
    }
    int run = (t == 0) ? 0 : ss[t - 1];
    for (int i = b; i < e; i++) {
        g_rowptr[i] = run;
        g_cursor[i] = run;
        int c = g_cnt[i];
        g_invdeg[i] = 1.0f / (float)(c > 0 ? c : 1);
        run += c;
    }
    if (t == 1023) g_rowptr[n] = ss[1023];
}

__global__ void k_fill(const int* __restrict__ edges, int E) {
    int e = blockIdx.x * blockDim.x + threadIdx.x;
    if (e < E) {
        int s = edges[2 * e];
        int d = edges[2 * e + 1];
        g_adj[atomicAdd(&g_cursor[s], 1)] = d;
        g_adj[atomicAdd(&g_cursor[d], 1)] = s;
    }
}

// deterministic adjacency order (sorted) + convert to byte offsets (nb*256)
#define SORT_BUF 96
__global__ void k_sortseg(int n) {
    int i = blockIdx.x * blockDim.x + threadIdx.x;
    if (i >= n) return;
    int b = g_rowptr[i], e = g_rowptr[i + 1];
    int len = e - b;
    if (len <= 0) return;
    if (len <= SORT_BUF) {
        int buf[SORT_BUF];
        for (int j = 0; j < len; j++) buf[j] = g_adj[b + j];
        for (int j = 1; j < len; j++) {
            int key = buf[j];
            int k = j - 1;
            while (k >= 0 && buf[k] > key) { buf[k + 1] = buf[k]; --k; }
            buf[k + 1] = key;
        }
        for (int j = 0; j < len; j++) g_adj[b + j] = buf[j] << 8;   // *256
    } else {
        for (int j = b + 1; j < e; j++) {
            int key = g_adj[j];
            int k = j - 1;
            while (k >= b && g_adj[k] > key) { g_adj[k + 1] = g_adj[k]; --k; }
            g_adj[k + 1] = key;
        }
        for (int j = b; j < e; j++) g_adj[j] <<= 8;
    }
}

// ======================= shared GEMM helpers =======================
#define SROW 272
#define STILE (128 * SROW)
#define T64   (64 * SROW)

__device__ __forceinline__ uint32_t smem_to_u32(const void* smem_ptr) {
    uint32_t addr;
    asm("{ .reg .u64 tmp; cvta.to.shared.u64 tmp, %1; cvt.u32.u64 %0, tmp; }"
        : "=r"(addr) : "l"(smem_ptr));
    return addr;
}

__device__ __forceinline__ void ldm_x4(uint32_t* r, uint32_t addr) {
    asm volatile("ldmatrix.sync.aligned.m8n8.x4.shared.b16 {%0,%1,%2,%3}, [%4];"
        : "=r"(r[0]), "=r"(r[1]), "=r"(r[2]), "=r"(r[3]) : "r"(addr));
}

__device__ __forceinline__ void mma16816(float* c, const uint32_t* a, const uint32_t* b) {
    asm volatile(
        "mma.sync.aligned.m16n8k16.row.col.f32.bf16.bf16.f32 "
        "{%0,%1,%2,%3}, {%4,%5,%6,%7}, {%8,%9}, {%0,%1,%2,%3};"
        : "+f"(c[0]), "+f"(c[1]), "+f"(c[2]), "+f"(c[3])
        : "r"(a[0]), "r"(a[1]), "r"(a[2]), "r"(a[3]), "r"(b[0]), "r"(b[1]));
}

__device__ __forceinline__ void cp16(uint32_t dst, const void* src) {
    asm volatile("cp.async.cg.shared.global [%0], [%1], 16;" :: "r"(dst), "l"(src));
}
#define CP_COMMIT() asm volatile("cp.async.commit_group;" ::: "memory")
#define CP_WAIT1()  asm volatile("cp.async.wait_group 1;" ::: "memory")

// ======================= tile GEMM (mm0 + ncu control) ================
#define SM_A_HI  0
#define SM_A_LO  (STILE)
#define SM_W1HI  (2 * STILE)
#define SM_W1LO  (3 * STILE)
#define SM_W0HI  (4 * STILE)
#define SM_W0LO  (5 * STILE)
#define SMEM_MM_TOTAL (6 * STILE)          // 208896 B

__global__ void __launch_bounds__(512, 1)
k_mm(const uint4* __restrict__ fhi, const uint4* __restrict__ flo,
     const uint4* __restrict__ w1hi, const uint4* __restrict__ w1lo,
     const uint4* __restrict__ w0hi, const uint4* __restrict__ w0lo,
     __half* __restrict__ hout, float* __restrict__ rawout, int M) {
    extern __shared__ char smem[];
    const int tid = threadIdx.x;
    const int wid = tid >> 5;
    const int lane = tid & 31;
    const int ph = wid >> 3;
    const int w8 = wid & 7;
    const int wm = w8 >> 1;
    const int wn = w8 & 1;
    const int rowBase = blockIdx.x * 128;

    const uint4 z4 = make_uint4(0, 0, 0, 0);
#pragma unroll 4
    for (int i = tid; i < 2048; i += 512) {
        int r = i >> 4, c = i & 15;
        uint32_t off = (uint32_t)r * SROW + (uint32_t)c * 16;
        bool ok = (rowBase + r) < M;
        size_t gi = (size_t)rowBase * 16 + i;
        *(uint4*)(smem + SM_A_HI + off) = ok ? fhi[gi] : z4;
        *(uint4*)(smem + SM_A_LO + off) = ok ? flo[gi] : z4;
        *(uint4*)(smem + SM_W1HI + off) = w1hi[i];
        *(uint4*)(smem + SM_W1LO + off) = w1lo[i];
        *(uint4*)(smem + SM_W0HI + off) = w0hi[i];
        *(uint4*)(smem + SM_W0LO + off) = w0lo[i];
    }
    __syncthreads();

    uint32_t sb = smem_to_u32(smem);
    const uint32_t aRowOff = (uint32_t)(wm * 32 + (lane & 15)) * SROW + ((lane >> 4) << 4);
    const uint32_t bRowCore = (uint32_t)(((lane >> 4) << 3) + (lane & 7)) * SROW
                            + (((lane >> 3) & 1) << 4);
    const int g = lane >> 2, tg = lane & 3;

    uint32_t wHi = sb + (ph ? SM_W0HI : SM_W1HI);
    uint32_t wLo = sb + (ph ? SM_W0LO : SM_W1LO);
    uint32_t aHiB = sb + SM_A_HI, aLoB = sb + SM_A_LO;

    float acc[2][8][4];
#pragma unroll
    for (int mt = 0; mt < 2; mt++)
#pragma unroll
        for (int nt = 0; nt < 8; nt++)
#pragma unroll
            for (int q = 0; q < 4; q++) acc[mt][nt][q] = 0.f;

#pragma unroll 1
    for (int ks = 0; ks < 8; ks++) {
        uint32_t kb = (uint32_t)ks * 32;
        uint32_t aH[2][4], aL[2][4];
        ldm_x4(aH[0], aHiB + aRowOff + kb);
        ldm_x4(aH[1], aHiB + aRowOff + 16 * SROW + kb);
        ldm_x4(aL[0], aLoB + aRowOff + kb);
        ldm_x4(aL[1], aLoB + aRowOff + 16 * SROW + kb);
        uint32_t bH[8][2], bL[8][2];
#pragma unroll
        for (int np = 0; np < 4; np++) {
            uint32_t rowoff = (uint32_t)(wn * 64 + np * 16) * SROW + bRowCore + kb;
            uint32_t tmp[4];
            ldm_x4(tmp, wHi + rowoff);
            bH[np * 2][0] = tmp[0]; bH[np * 2][1] = tmp[1];
            bH[np * 2 + 1][0] = tmp[2]; bH[np * 2 + 1][1] = tmp[3];
            ldm_x4(tmp, wLo + rowoff);
            bL[np * 2][0] = tmp[0]; bL[np * 2][1] = tmp[1];
            bL[np * 2 + 1][0] = tmp[2]; bL[np * 2 + 1][1] = tmp[3];
        }
#pragma unroll
        for (int mt = 0; mt < 2; mt++)
#pragma unroll
            for (int nt = 0; nt < 8; nt++) {
                mma16816(acc[mt][nt], aH[mt], bH[nt]);
                mma16816(acc[mt][nt], aH[mt], bL[nt]);
                mma16816(acc[mt][nt], aL[mt], bH[nt]);
            }
    }

#pragma unroll
    for (int mt = 0; mt < 2; mt++) {
        int row0 = rowBase + wm * 32 + mt * 16 + g;
#pragma unroll
        for (int nt = 0; nt < 8; nt++) {
            int col = wn * 64 + nt * 8 + tg * 2;
            if (ph == 0) {
                if (row0 < M)
                    *(__half2*)(hout + (size_t)row0 * 128 + col) =
                        __floats2half2_rn(acc[mt][nt][0], acc[mt][nt][1]);
                if (row0 + 8 < M)
                    *(__half2*)(hout + (size_t)(row0 + 8) * 128 + col) =
                        __floats2half2_rn(acc[mt][nt][2], acc[mt][nt][3]);
            } else {
                if (row0 < M)
                    *(float2*)(rawout + (size_t)row0 * 128 + col) =
                        make_float2(acc[mt][nt][0], acc[mt][nt][1]);
                if (row0 + 8 < M)
                    *(float2*)(rawout + (size_t)(row0 + 8) * 128 + col) =
                        make_float2(acc[mt][nt][2], acc[mt][nt][3]);
            }
        }
    }
}

// ======================= persistent GEMM (layers 1-3) ================
// Weights loaded once per SM; 64-row A tiles double-buffered via cp.async.
#define SMP_W  0
#define SMP_A  (4 * STILE)
#define SMEM_MMP_TOTAL (6 * STILE)

__global__ void __launch_bounds__(512, 1)
k_mmp(const uint4* __restrict__ fhi, const uint4* __restrict__ flo,
      const uint4* __restrict__ w1hi, const uint4* __restrict__ w1lo,
      const uint4* __restrict__ w0hi, const uint4* __restrict__ w0lo,
      __half* __restrict__ hout, float* __restrict__ rawout, int M, int nTiles) {
    extern __shared__ char smem[];
    uint32_t sb = smem_to_u32(smem);
    const int tid = threadIdx.x;
    const int wid = tid >> 5;
    const int lane = tid & 31;
    const int ph = wid >> 3;
    const int w8 = wid & 7;
    const int wm = w8 >> 1;        // 16-row strip within 64-row tile
    const int wn = w8 & 1;

    {
        const uint4* wsrc[4] = {w1hi, w1lo, w0hi, w0lo};
#pragma unroll
        for (int it = 0; it < 16; it++) {
            int i = tid + 512 * it;
            int tl = i >> 11, j = i & 2047, r = j >> 4, c = j & 15;
            *(uint4*)(smem + SMP_W + tl * STILE + (uint32_t)r * SROW + (uint32_t)c * 16)
                = wsrc[tl][j];
        }
    }

    const int stride = gridDim.x;
    int t0 = blockIdx.x;

    if (t0 < nTiles) {
        int base = t0 * 64;
        uint32_t dst = sb + SMP_A;
#pragma unroll
        for (int it = 0; it < 4; it++) {
            int i = tid + 512 * it;
            int half = i >> 10, j = i & 1023, r = j >> 4, c = j & 15;
            int grow = base + r; grow = grow < M ? grow : M - 1;
            const uint4* src = (half ? flo : fhi) + (size_t)grow * 16 + c;
            cp16(dst + half * T64 + (uint32_t)r * SROW + (uint32_t)c * 16, src);
        }
    }
    CP_COMMIT();

    const uint32_t aRowOff = (uint32_t)(wm * 16 + (lane & 15)) * SROW + ((lane >> 4) << 4);
    const uint32_t bRowCore = (uint32_t)(((lane >> 4) << 3) + (lane & 7)) * SROW
                            + (((lane >> 3) & 1) << 4);
    const int g = lane >> 2, tg = lane & 3;
    const uint32_t wHi = sb + SMP_W + (ph ? 2 : 0) * STILE;
    const uint32_t wLo = sb + SMP_W + (ph ? 3 : 1) * STILE;

    int buf = 0;
    for (int t = t0; t < nTiles; t += stride) {
        int tn = t + stride;
        if (tn < nTiles) {
            int base = tn * 64;
            uint32_t dst = sb + SMP_A + (buf ^ 1) * (2 * T64);
#pragma unroll
            for (int it = 0; it < 4; it++) {
                int i = tid + 512 * it;
                int half = i >> 10, j = i & 1023, r = j >> 4, c = j & 15;
                int grow = base + r; grow = grow < M ? grow : M - 1;
                const uint4* src = (half ? flo : fhi) + (size_t)grow * 16 + c;
                cp16(dst + half * T64 + (uint32_t)r * SROW + (uint32_t)c * 16, src);
            }
        }
        CP_COMMIT();
        CP_WAIT1();
        __syncthreads();

        uint32_t aHiB = sb + SMP_A + buf * (2 * T64);
        uint32_t aLoB = aHiB + T64;

        float acc[8][4];
#pragma unroll
        for (int nt = 0; nt < 8; nt++)
#pragma unroll
            for (int q = 0; q < 4; q++) acc[nt][q] = 0.f;

#pragma unroll 1
        for (int ks = 0; ks < 8; ks++) {
            uint32_t kb = (uint32_t)ks * 32;
            uint32_t aH[4], aL[4];
            ldm_x4(aH, aHiB + aRowOff + kb);
            ldm_x4(aL, aLoB + aRowOff + kb);
            uint32_t bH[8][2], bL[8][2];
#pragma unroll
            for (int np = 0; np < 4; np++) {
                uint32_t rowoff = (uint32_t)(wn * 64 + np * 16) * SROW + bRowCore + kb;
                uint32_t tmp[4];
                ldm_x4(tmp, wHi + rowoff);
                bH[np * 2][0] = tmp[0]; bH[np * 2][1] = tmp[1];
                bH[np * 2 + 1][0] = tmp[2]; bH[np * 2 + 1][1] = tmp[3];
                ldm_x4(tmp, wLo + rowoff);
                bL[np * 2][0] = tmp[0]; bL[np * 2][1] = tmp[1];
                bL[np * 2 + 1][0] = tmp[2]; bL[np * 2 + 1][1] = tmp[3];
            }
#pragma unroll
            for (int nt = 0; nt < 8; nt++) {
                mma16816(acc[nt], aH, bH[nt]);
                mma16816(acc[nt], aH, bL[nt]);
                mma16816(acc[nt], aL, bH[nt]);
            }
        }

        int row0 = t * 64 + wm * 16 + g;
#pragma unroll
        for (int nt = 0; nt < 8; nt++) {
            int col = wn * 64 + nt * 8 + tg * 2;
            if (ph == 0) {
                if (row0 < M)
                    *(__half2*)(hout + (size_t)row0 * 128 + col) =
                        __floats2half2_rn(acc[nt][0], acc[nt][1]);
                if (row0 + 8 < M)
                    *(__half2*)(hout + (size_t)(row0 + 8) * 128 + col) =
                        __floats2half2_rn(acc[nt][2], acc[nt][3]);
            } else {
                if (row0 < M)
                    *(float2*)(rawout + (size_t)row0 * 128 + col) =
                        make_float2(acc[nt][0], acc[nt][1]);
                if (row0 + 8 < M)
                    *(float2*)(rawout + (size_t)(row0 + 8) * 128 + col) =
                        make_float2(acc[nt][2], acc[nt][3]);
            }
        }
        __syncthreads();
        buf ^= 1;
    }
}

// ============ fused aggregate + epilogue: LDG.128 half-warp gathers, adj prefetch ============
__device__ __forceinline__ void addu4(float* a, uint4 u) {
    float2 t;
    t = __half22float2(*(__half2*)&u.x); a[0] += t.x; a[1] += t.y;
    t = __half22float2(*(__half2*)&u.y); a[2] += t.x; a[3] += t.y;
    t = __half22float2(*(__half2*)&u.z); a[4] += t.x; a[5] += t.y;
    t = __half22float2(*(__half2*)&u.w); a[6] += t.x; a[7] += t.y;
}

__global__ void __launch_bounds__(64)
k_aggepi(const __half* __restrict__ h, const float4* __restrict__ raw,
         const float* __restrict__ bias, const float4* __restrict__ res,
         float4* __restrict__ outF,
         uint2* __restrict__ fhi, uint2* __restrict__ flo,
         int n, int mode) {
    int node = (blockIdx.x * blockDim.x + threadIdx.x) >> 5;
    if (node >= n) return;
    const int lane = threadIdx.x & 31;
    const int half = lane >> 4;
    const int ci = lane & 15;
    int b = g_rowptr[node], e = g_rowptr[node + 1];
    const char* hb = (const char*)h;

    float acc0[8], acc1[8];
#pragma unroll
    for (int j = 0; j < 8; j++) { acc0[j] = 0.f; acc1[j] = 0.f; }

    int p = b;
    int nfull = (e - b) >> 4;     // full 16-neighbor iterations
    if (nfull > 0) {
        int off[8];
#pragma unroll
        for (int q = 0; q < 8; q++) off[q] = g_adj[p + 2 * q + half];
        for (int it = 0; it < nfull; it++) {
            // issue gathers for CURRENT offsets first (already resident in regs)
            uint4 u[8];
#pragma unroll
            for (int q = 0; q < 8; q++)
                u[q] = __ldcg((const uint4*)(hb + off[q]) + ci);
            // prefetch NEXT iteration's offsets while gathers are in flight
            int pn = p + 16;
            if (it + 1 < nfull) {
#pragma unroll
                for (int q = 0; q < 8; q++) off[q] = g_adj[pn + 2 * q + half];
            }
#pragma unroll
            for (int q = 0; q < 8; q++) addu4((q & 1) ? acc1 : acc0, u[q]);
            p = pn;
        }
    }
    if (p + 8 <= e) {
        uint4 u[4];
#pragma unroll
        for (int q = 0; q < 4; q++) {
            int off = g_adj[p + 2 * q + half];
            u[q] = __ldcg((const uint4*)(hb + off) + ci);
        }
#pragma unroll
        for (int q = 0; q < 4; q++) addu4((q & 1) ? acc1 : acc0, u[q]);
        p += 8;
    }
    for (; p < e; p += 2) {
        int idx = p + half;
        if (idx < e) {
            int off = g_adj[idx];
            uint4 u = __ldcg((const uint4*)(hb + off) + ci);
            addu4(acc0, u);
        }
    }

    float tot[8];
#pragma unroll
    for (int j = 0; j < 8; j++) tot[j] = acc0[j] + acc1[j];
#pragma unroll
    for (int j = 0; j < 8; j++)
        tot[j] += __shfl_xor_sync(0xffffffffu, tot[j], 16);

    if (half == 0) {
        float s = g_invdeg[node];
        size_t idx = (size_t)node * 32 + (size_t)ci * 2;
#pragma unroll
        for (int k = 0; k < 2; k++) {
            float4 v = raw[idx + k];
            float4 bb = ((const float4*)bias)[ci * 2 + k];
            v.x += bb.x + tot[4 * k + 0] * s;
            v.y += bb.y + tot[4 * k + 1] * s;
            v.z += bb.z + tot[4 * k + 2] * s;
            v.w += bb.w + tot[4 * k + 3] * s;
            if (mode == 2) {
                float4 r = res[idx + k];
                v.x += r.x; v.y += r.y; v.z += r.z; v.w += r.w;
            }
            if (mode >= 1) {
                v.x = fmaxf(v.x, 0.f); v.y = fmaxf(v.y, 0.f);
                v.z = fmaxf(v.z, 0.f); v.w = fmaxf(v.w, 0.f);
            }
            if (mode == 2) {
                outF[idx + k] = v;
            } else {
                uint2 hi, lo;
                split4(v, hi, lo);
                fhi[idx + k] = hi;
                flo[idx + k] = lo;
            }
        }
    }
}

// ======================= launch =======================
extern "C" void kernel_launch(void* const* d_in, const int* in_sizes, int n_in,
                              void* d_out, int out_size) {
    const float* features = (const float*)d_in[0];
    const int*   edges    = (const int*)d_in[1];
    const float* W0f = (const float*)d_in[3];
    const float* W1f = (const float*)d_in[4];
    const float* bf  = (const float*)d_in[5];
    const float* W0h = (const float*)d_in[6];
    const float* W1h = (const float*)d_in[7];
    const float* bh  = (const float*)d_in[8];

    int Nn = in_sizes[0] / D;
    int Ee = in_sizes[1] / 2;

    uint4 *fhi, *flo, *whi, *wlo;
    __half* hbuf;
    float4* rawb;
    int* cntp;
    cudaGetSymbolAddress((void**)&fhi, g_fhi4);
    cudaGetSymbolAddress((void**)&flo, g_flo4);
    cudaGetSymbolAddress((void**)&whi, g_Whi4);
    cudaGetSymbolAddress((void**)&wlo, g_Wlo4);
    cudaGetSymbolAddress((void**)&hbuf, g_h);
    cudaGetSymbolAddress((void**)&rawb, g_raw);
    cudaGetSymbolAddress((void**)&cntp, g_cnt);

    cudaFuncSetAttribute(k_mm,  cudaFuncAttributeMaxDynamicSharedMemorySize, SMEM_MM_TOTAL);
    cudaFuncSetAttribute(k_mmp, cudaFuncAttributeMaxDynamicSharedMemorySize, SMEM_MMP_TOTAL);

    int dev = 0, sms = 148;
    cudaGetDevice(&dev);
    cudaDeviceGetAttribute(&sms, cudaDevAttrMultiProcessorCount, dev);
    if (sms < 1) sms = 148;

    int vblocks = (Nn * 32 + 255) / 256;
    int gblocks = (Nn + 127) / 128;
    int nTiles64 = (Nn + 63) / 64;
    int ablocks = (Nn * 32 + 63) / 64;

    cudaStream_t s0 = (cudaStream_t)0;
    cudaStream_t s1;
    cudaStreamCreateWithFlags(&s1, cudaStreamNonBlocking);

    cudaEvent_t evFork, evCSR;
    cudaEventCreateWithFlags(&evFork, cudaEventDisableTiming);
    cudaEventCreateWithFlags(&evCSR, cudaEventDisableTiming);

    cudaEventRecord(evFork, s0);
    cudaStreamWaitEvent(s1, evFork, 0);

    // s0: conv -> mm0 (tile kernel, 4th submission = ncu control); s1: CSR chain
    k_conv<<<vblocks, 256, 0, s0>>>(features, W0f, W1f, W0h, W1h, Nn);
    cudaMemsetAsync(cntp, 0, (size_t)Nn * sizeof(int), s1);
    k_count<<<(Ee + 255) / 256, 256, 0, s1>>>(edges, Ee);
    k_scan<<<1, 1024, 0, s1>>>(Nn);
    k_mm<<<gblocks, 512, SMEM_MM_TOTAL, s0>>>(fhi, flo,
        whi + 0 * 2048, wlo + 0 * 2048,
        whi + 1 * 2048, wlo + 1 * 2048,
        hbuf, (float*)rawb, Nn);
    k_fill<<<(Ee + 255) / 256, 256, 0, s1>>>(edges, Ee);
    k_sortseg<<<(Nn + 127) / 128, 128, 0, s1>>>(Nn);
    cudaEventRecord(evCSR, s1);
    cudaStreamWaitEvent(s0, evCSR, 0);

    for (int l = 0; l < 4; l++) {
        if (l > 0) {
            k_mmp<<<sms, 512, SMEM_MMP_TOTAL, s0>>>(fhi, flo,
                whi + (size_t)(2 * l) * 2048,     wlo + (size_t)(2 * l) * 2048,
                whi + (size_t)(2 * l + 1) * 2048, wlo + (size_t)(2 * l + 1) * 2048,
                hbuf, (float*)rawb, Nn, nTiles64);
        }
        const float* bb = (l == 0) ? bf : bh + (size_t)(l - 1) * D;
        int mode = (l == 0) ? 0 : (l == 3 ? 2 : 1);
        k_aggepi<<<ablocks, 64, 0, s0>>>(hbuf, rawb, bb, (const float4*)features,
                                         (float4*)d_out, (uint2*)fhi, (uint2*)flo,
                                         Nn, mode);
    }
}